// round 1
// baseline (speedup 1.0000x reference)
#include <cuda_runtime.h>
#include <cuda_bf16.h>

// Problem constants (match reference setup_inputs)
#define B_TOT   16
#define NV      6890
#define NF      13776
#define NPAIR   8              // B/2
#define NFACE2  (2*NF)         // 27552 faces per pair
#define C_PER   65536          // collisions per pair
#define SIGMA_F 1e-4f
#define EPS_F   1e-9f
#define THRESH_F 2000.0f
#define WEIGHT_F 0.1f

#define COLL_TOTAL (NPAIR * C_PER)        // 524288
#define FACE_TOTAL (NPAIR * NFACE2)       // 220416
#define BLK 256
#define COLL_BLOCKS (COLL_TOTAL / BLK)    // 2048  (256 blocks per pair)

// Scratch (device globals — no runtime allocation allowed)
__device__ float4 g_intr[FACE_TOTAL * 3]; // v0,v1,v2 per (pair,face)   ~10.6 MB
__device__ float4 g_recv[FACE_TOTAL * 2]; // {n.xyz, radius},{c.xyz,0}  ~7.1 MB
__device__ float  g_partial[COLL_BLOCKS]; // per-block partial sums

// ---------------------------------------------------------------------------
// Kernel 1: per-(pair,face) triangle precompute
// ---------------------------------------------------------------------------
__global__ void __launch_bounds__(BLK)
precompute_kernel(const float* __restrict__ verts,
                  const float* __restrict__ trans,
                  const int*   __restrict__ faces)
{
    int idx = blockIdx.x * BLK + threadIdx.x;
    if (idx >= FACE_TOTAL) return;

    int p = idx / NFACE2;
    int f = idx - p * NFACE2;
    int second = (f >= NF);
    int person = 2 * p + second;
    int frow   = second ? (f - NF) : f;

    int i0 = __ldg(&faces[frow * 3 + 0]);
    int i1 = __ldg(&faces[frow * 3 + 1]);
    int i2 = __ldg(&faces[frow * 3 + 2]);

    float tx = __ldg(&trans[person * 3 + 0]);
    float ty = __ldg(&trans[person * 3 + 1]);
    float tz = __ldg(&trans[person * 3 + 2]);

    const float* vb = verts + (size_t)person * NV * 3;

    float v0x = __ldg(&vb[i0*3+0]) + tx, v0y = __ldg(&vb[i0*3+1]) + ty, v0z = __ldg(&vb[i0*3+2]) + tz;
    float v1x = __ldg(&vb[i1*3+0]) + tx, v1y = __ldg(&vb[i1*3+1]) + ty, v1z = __ldg(&vb[i1*3+2]) + tz;
    float v2x = __ldg(&vb[i2*3+0]) + tx, v2y = __ldg(&vb[i2*3+1]) + ty, v2z = __ldg(&vb[i2*3+2]) + tz;

    // receiver-frame quantities (also used when this face is an intruder: raw verts)
    float e1x = v1x - v0x, e1y = v1y - v0y, e1z = v1z - v0z;
    float e2x = v2x - v0x, e2y = v2y - v0y, e2z = v2z - v0z;

    float nx = e1y * e2z - e1z * e2y;
    float ny = e1z * e2x - e1x * e2z;
    float nz = e1x * e2y - e1y * e2x;
    float nn = sqrtf(nx*nx + ny*ny + nz*nz);
    float inv = 1.0f / (nn + EPS_F);
    nx *= inv; ny *= inv; nz *= inv;

    float cx = (v0x + v1x + v2x) * (1.0f / 3.0f);
    float cy = (v0y + v1y + v2y) * (1.0f / 3.0f);
    float cz = (v0z + v1z + v2z) * (1.0f / 3.0f);

    float d0x = v0x - cx, d0y = v0y - cy, d0z = v0z - cz;
    float d1x = v1x - cx, d1y = v1y - cy, d1z = v1z - cz;
    float d2x = v2x - cx, d2y = v2y - cy, d2z = v2z - cz;
    float r0 = sqrtf(d0x*d0x + d0y*d0y + d0z*d0z);
    float r1 = sqrtf(d1x*d1x + d1y*d1y + d1z*d1z);
    float r2 = sqrtf(d2x*d2x + d2y*d2y + d2z*d2z);
    float radius = fmaxf(r0, fmaxf(r1, r2));

    g_intr[idx*3 + 0] = make_float4(v0x, v0y, v0z, 0.0f);
    g_intr[idx*3 + 1] = make_float4(v1x, v1y, v1z, 0.0f);
    g_intr[idx*3 + 2] = make_float4(v2x, v2y, v2z, 0.0f);

    g_recv[idx*2 + 0] = make_float4(nx, ny, nz, radius);
    g_recv[idx*2 + 1] = make_float4(cx, cy, cz, 0.0f);
}

// ---------------------------------------------------------------------------
// Kernel 2: per-collision field evaluation + deterministic block reduction
// ---------------------------------------------------------------------------
__global__ void __launch_bounds__(BLK)
collide_kernel(const int* __restrict__ cidx)
{
    int g = blockIdx.x * BLK + threadIdx.x;   // global collision id
    int p = g >> 16;                          // C_PER = 65536 per pair

    int2 ci = ((const int2*)cidx)[g];

    float contrib = 0.0f;
    if (ci.x != ci.y) {
        int base = p * NFACE2;
        int ri = (base + ci.y) * 2;
        int ii = (base + ci.x) * 3;

        float4 rA = g_recv[ri];       // n.xyz, radius
        float4 rB = g_recv[ri + 1];   // c.xyz
        float4 a0 = g_intr[ii];
        float4 a1 = g_intr[ii + 1];
        float4 a2 = g_intr[ii + 2];

        float nx = rA.x, ny = rA.y, nz = rA.z;
        float radius = rA.w;
        float cx = rB.x, cy = rB.y, cz = rB.z;
        float invr = 1.0f / (radius + EPS_F);

        float vx[3] = {a0.x, a1.x, a2.x};
        float vy[3] = {a0.y, a1.y, a2.y};
        float vz[3] = {a0.z, a1.z, a2.z};

        #pragma unroll
        for (int v = 0; v < 3; ++v) {
            float dx = vx[v] - cx, dy = vy[v] - cy, dz = vz[v] - cz;
            float d  = dx*nx + dy*ny + dz*nz;
            float rx = dx - d*nx, ry = dy - d*ny, rz = dz - d*nz;
            float radial = sqrtf(rx*rx + ry*ry + rz*rz);
            float f1 = fmaxf(-d / SIGMA_F, 0.0f);
            float f2 = fmaxf(1.0f - radial * invr, 0.0f);
            float fld = f1 * f2;
            contrib += fld * fld;
        }
    }

    // deterministic block reduction (warp shuffle + smem)
    #pragma unroll
    for (int off = 16; off > 0; off >>= 1)
        contrib += __shfl_down_sync(0xffffffffu, contrib, off);

    __shared__ float ws[BLK / 32];
    int warp = threadIdx.x >> 5;
    int lane = threadIdx.x & 31;
    if (lane == 0) ws[warp] = contrib;
    __syncthreads();

    if (warp == 0) {
        float v = (lane < BLK / 32) ? ws[lane] : 0.0f;
        #pragma unroll
        for (int off = 4; off > 0; off >>= 1)
            v += __shfl_down_sync(0xffffffffu, v, off);
        if (lane == 0) g_partial[blockIdx.x] = v;
    }
}

// ---------------------------------------------------------------------------
// Kernel 3: finalize — per-pair pen, threshold/sigmoid epilogue, scalar out
// ---------------------------------------------------------------------------
__global__ void __launch_bounds__(BLK)
finalize_kernel(float* __restrict__ out)
{
    __shared__ float pen_s[NPAIR];
    int warp = threadIdx.x >> 5;   // 8 warps, one per pair
    int lane = threadIdx.x & 31;
    const int PER_PAIR = COLL_BLOCKS / NPAIR; // 256 partials per pair

    float s = 0.0f;
    for (int j = lane; j < PER_PAIR; j += 32)
        s += g_partial[warp * PER_PAIR + j];
    #pragma unroll
    for (int off = 16; off > 0; off >>= 1)
        s += __shfl_down_sync(0xffffffffu, s, off);
    if (lane == 0) pen_s[warp] = s;
    __syncthreads();

    if (threadIdx.x == 0) {
        float cnt = 0.0f, vs = 0.0f;
        #pragma unroll
        for (int pp = 0; pp < NPAIR; ++pp) {
            float pen = pen_s[pp];
            if (pen < THRESH_F) {
                cnt += 1.0f;
                float sg = 1.0f / (1.0f + expf(-pen / THRESH_F));
                vs += (sg - 0.5f);
            }
        }
        float loss = (cnt > 0.0f) ? (vs / fmaxf(cnt, 1.0f)) : 0.0f;
        out[0] = loss * WEIGHT_F;
    }
}

// ---------------------------------------------------------------------------
extern "C" void kernel_launch(void* const* d_in, const int* in_sizes, int n_in,
                              void* d_out, int out_size)
{
    const float* verts = (const float*)d_in[0];   // [16, 6890, 3]
    const float* trans = (const float*)d_in[1];   // [16, 3]
    const int*   faces = (const int*)  d_in[2];   // [13776, 3]
    const int*   cidx  = (const int*)  d_in[3];   // [8, 65536, 2]
    float* out = (float*)d_out;

    (void)in_sizes; (void)n_in; (void)out_size;

    int pre_blocks = (FACE_TOTAL + BLK - 1) / BLK; // 861
    precompute_kernel<<<pre_blocks, BLK>>>(verts, trans, faces);
    collide_kernel<<<COLL_BLOCKS, BLK>>>(cidx);
    finalize_kernel<<<1, BLK>>>(out);
}

// round 2
// speedup vs baseline: 1.0012x; 1.0012x over previous
#include <cuda_runtime.h>
#include <cuda_bf16.h>

// Problem constants (match reference setup_inputs)
#define B_TOT   16
#define NV      6890
#define NF      13776
#define NPAIR   8              // B/2
#define NFACE2  (2*NF)         // 27552 faces per pair
#define C_PER   65536          // collisions per pair
#define SIGMA_F 1e-4f
#define EPS_F   1e-9f
#define THRESH_F 2000.0f
#define WEIGHT_F 0.1f

#define COLL_TOTAL (NPAIR * C_PER)        // 524288
#define FACE_TOTAL (NPAIR * NFACE2)       // 220416
#define BLK 256
#define COLL_BLOCKS (COLL_TOTAL / BLK)    // 2048  (256 blocks per pair)

// Scratch (device globals — no runtime allocation allowed)
__device__ float4 g_intr[FACE_TOTAL * 3]; // v0,v1,v2 per (pair,face)   ~10.6 MB
__device__ float4 g_recv[FACE_TOTAL * 2]; // {n.xyz, radius},{c.xyz,0}  ~7.1 MB
__device__ float  g_partial[COLL_BLOCKS]; // per-block partial sums

// ---------------------------------------------------------------------------
// Kernel 1: per-(pair,face) triangle precompute
// ---------------------------------------------------------------------------
__global__ void __launch_bounds__(BLK)
precompute_kernel(const float* __restrict__ verts,
                  const float* __restrict__ trans,
                  const int*   __restrict__ faces)
{
    int idx = blockIdx.x * BLK + threadIdx.x;
    if (idx >= FACE_TOTAL) return;

    int p = idx / NFACE2;
    int f = idx - p * NFACE2;
    int second = (f >= NF);
    int person = 2 * p + second;
    int frow   = second ? (f - NF) : f;

    int i0 = __ldg(&faces[frow * 3 + 0]);
    int i1 = __ldg(&faces[frow * 3 + 1]);
    int i2 = __ldg(&faces[frow * 3 + 2]);

    float tx = __ldg(&trans[person * 3 + 0]);
    float ty = __ldg(&trans[person * 3 + 1]);
    float tz = __ldg(&trans[person * 3 + 2]);

    const float* vb = verts + (size_t)person * NV * 3;

    float v0x = __ldg(&vb[i0*3+0]) + tx, v0y = __ldg(&vb[i0*3+1]) + ty, v0z = __ldg(&vb[i0*3+2]) + tz;
    float v1x = __ldg(&vb[i1*3+0]) + tx, v1y = __ldg(&vb[i1*3+1]) + ty, v1z = __ldg(&vb[i1*3+2]) + tz;
    float v2x = __ldg(&vb[i2*3+0]) + tx, v2y = __ldg(&vb[i2*3+1]) + ty, v2z = __ldg(&vb[i2*3+2]) + tz;

    // receiver-frame quantities (also used when this face is an intruder: raw verts)
    float e1x = v1x - v0x, e1y = v1y - v0y, e1z = v1z - v0z;
    float e2x = v2x - v0x, e2y = v2y - v0y, e2z = v2z - v0z;

    float nx = e1y * e2z - e1z * e2y;
    float ny = e1z * e2x - e1x * e2z;
    float nz = e1x * e2y - e1y * e2x;
    float nn = sqrtf(nx*nx + ny*ny + nz*nz);
    float inv = 1.0f / (nn + EPS_F);
    nx *= inv; ny *= inv; nz *= inv;

    float cx = (v0x + v1x + v2x) * (1.0f / 3.0f);
    float cy = (v0y + v1y + v2y) * (1.0f / 3.0f);
    float cz = (v0z + v1z + v2z) * (1.0f / 3.0f);

    float d0x = v0x - cx, d0y = v0y - cy, d0z = v0z - cz;
    float d1x = v1x - cx, d1y = v1y - cy, d1z = v1z - cz;
    float d2x = v2x - cx, d2y = v2y - cy, d2z = v2z - cz;
    float r0 = sqrtf(d0x*d0x + d0y*d0y + d0z*d0z);
    float r1 = sqrtf(d1x*d1x + d1y*d1y + d1z*d1z);
    float r2 = sqrtf(d2x*d2x + d2y*d2y + d2z*d2z);
    float radius = fmaxf(r0, fmaxf(r1, r2));

    g_intr[idx*3 + 0] = make_float4(v0x, v0y, v0z, 0.0f);
    g_intr[idx*3 + 1] = make_float4(v1x, v1y, v1z, 0.0f);
    g_intr[idx*3 + 2] = make_float4(v2x, v2y, v2z, 0.0f);

    g_recv[idx*2 + 0] = make_float4(nx, ny, nz, radius);
    g_recv[idx*2 + 1] = make_float4(cx, cy, cz, 0.0f);
}

// ---------------------------------------------------------------------------
// Kernel 2: per-collision field evaluation + deterministic block reduction
// ---------------------------------------------------------------------------
__global__ void __launch_bounds__(BLK)
collide_kernel(const int* __restrict__ cidx)
{
    int g = blockIdx.x * BLK + threadIdx.x;   // global collision id
    int p = g >> 16;                          // C_PER = 65536 per pair

    int2 ci = ((const int2*)cidx)[g];

    float contrib = 0.0f;
    if (ci.x != ci.y) {
        int base = p * NFACE2;
        int ri = (base + ci.y) * 2;
        int ii = (base + ci.x) * 3;

        float4 rA = g_recv[ri];       // n.xyz, radius
        float4 rB = g_recv[ri + 1];   // c.xyz
        float4 a0 = g_intr[ii];
        float4 a1 = g_intr[ii + 1];
        float4 a2 = g_intr[ii + 2];

        float nx = rA.x, ny = rA.y, nz = rA.z;
        float radius = rA.w;
        float cx = rB.x, cy = rB.y, cz = rB.z;
        float invr = 1.0f / (radius + EPS_F);

        float vx[3] = {a0.x, a1.x, a2.x};
        float vy[3] = {a0.y, a1.y, a2.y};
        float vz[3] = {a0.z, a1.z, a2.z};

        #pragma unroll
        for (int v = 0; v < 3; ++v) {
            float dx = vx[v] - cx, dy = vy[v] - cy, dz = vz[v] - cz;
            float d  = dx*nx + dy*ny + dz*nz;
            float rx = dx - d*nx, ry = dy - d*ny, rz = dz - d*nz;
            float radial = sqrtf(rx*rx + ry*ry + rz*rz);
            float f1 = fmaxf(-d / SIGMA_F, 0.0f);
            float f2 = fmaxf(1.0f - radial * invr, 0.0f);
            float fld = f1 * f2;
            contrib += fld * fld;
        }
    }

    // deterministic block reduction (warp shuffle + smem)
    #pragma unroll
    for (int off = 16; off > 0; off >>= 1)
        contrib += __shfl_down_sync(0xffffffffu, contrib, off);

    __shared__ float ws[BLK / 32];
    int warp = threadIdx.x >> 5;
    int lane = threadIdx.x & 31;
    if (lane == 0) ws[warp] = contrib;
    __syncthreads();

    if (warp == 0) {
        float v = (lane < BLK / 32) ? ws[lane] : 0.0f;
        #pragma unroll
        for (int off = 4; off > 0; off >>= 1)
            v += __shfl_down_sync(0xffffffffu, v, off);
        if (lane == 0) g_partial[blockIdx.x] = v;
    }
}

// ---------------------------------------------------------------------------
// Kernel 3: finalize — per-pair pen, threshold/sigmoid epilogue, scalar out
// ---------------------------------------------------------------------------
__global__ void __launch_bounds__(BLK)
finalize_kernel(float* __restrict__ out)
{
    __shared__ float pen_s[NPAIR];
    int warp = threadIdx.x >> 5;   // 8 warps, one per pair
    int lane = threadIdx.x & 31;
    const int PER_PAIR = COLL_BLOCKS / NPAIR; // 256 partials per pair

    float s = 0.0f;
    for (int j = lane; j < PER_PAIR; j += 32)
        s += g_partial[warp * PER_PAIR + j];
    #pragma unroll
    for (int off = 16; off > 0; off >>= 1)
        s += __shfl_down_sync(0xffffffffu, s, off);
    if (lane == 0) pen_s[warp] = s;
    __syncthreads();

    if (threadIdx.x == 0) {
        float cnt = 0.0f, vs = 0.0f;
        #pragma unroll
        for (int pp = 0; pp < NPAIR; ++pp) {
            float pen = pen_s[pp];
            if (pen < THRESH_F) {
                cnt += 1.0f;
                float sg = 1.0f / (1.0f + expf(-pen / THRESH_F));
                vs += (sg - 0.5f);
            }
        }
        float loss = (cnt > 0.0f) ? (vs / fmaxf(cnt, 1.0f)) : 0.0f;
        out[0] = loss * WEIGHT_F;
    }
}

// ---------------------------------------------------------------------------
extern "C" void kernel_launch(void* const* d_in, const int* in_sizes, int n_in,
                              void* d_out, int out_size)
{
    const float* verts = (const float*)d_in[0];   // [16, 6890, 3]
    const float* trans = (const float*)d_in[1];   // [16, 3]
    const int*   faces = (const int*)  d_in[2];   // [13776, 3]
    const int*   cidx  = (const int*)  d_in[3];   // [8, 65536, 2]
    float* out = (float*)d_out;

    (void)in_sizes; (void)n_in; (void)out_size;

    int pre_blocks = (FACE_TOTAL + BLK - 1) / BLK; // 861
    precompute_kernel<<<pre_blocks, BLK>>>(verts, trans, faces);
    collide_kernel<<<COLL_BLOCKS, BLK>>>(cidx);
    finalize_kernel<<<1, BLK>>>(out);
}